// round 13
// baseline (speedup 1.0000x reference)
#include <cuda_runtime.h>
#include <cstdint>

// Problem shape (fixed)
#define B_  32
#define L_  512
#define D_  768
#define H_  100
#define C_  45
#define M_  (B_ * L_)           // 16384 rows
#define NB  48                  // padded N
#define BM  64                  // rows per CTA -> 256 CTAs
#define NCHUNK 6                // 6 chunks of 128 f32 k
#define GT  1024
#define NSTG 3                  // cp.async pipeline stages

#define ASUB 8192               // A subtile (64 rows * 128B = 32 f32 k)
#define ATOT 32768              // A per stage (4 subtiles, k=128)
#define BSUB 6144               // B subtile (48 rows * 128B)
#define BTOT 24576              // B per stage (4 subtiles)
#define BCH  BTOT               // B bytes per chunk in global
#define BUFSZ (ATOT + BTOT)     // 57344 per stage
// Reduction scratch reuses stages 0/1 (free after the ch=5 publish barrier).
#define OFF_CVEC (NSTG*BUFSZ)   // 172032
#define OFF_GS   (OFF_CVEC + 192)
#define SMEM_USE (OFF_GS + 256)
#define SMEM_BYTES (SMEM_USE + 1024)

#define SW(o) ((o) ^ (((o) >> 3) & 0x70))

// Device scratch. g_Wb: fused weight, tf32(f32) SW128 pre-swizzled.
// Layout: [chunk 0..5][ka 0..3][48 rows x 128B].
__device__ unsigned char g_Wb[NCHUNK * BCH];
__device__ float g_cvec[NB];

// ---------------------------------------------------------------------------
// PTX helpers (arch-portable: ldmatrix sm_75+, mma.tf32 sm_80+, cp.async sm_80+)
// ---------------------------------------------------------------------------
__device__ __forceinline__ uint32_t smem_u32(const void* p) {
    uint32_t a;
    asm("{ .reg .u64 t; cvta.to.shared.u64 t, %1; cvt.u32.u64 %0, t; }"
        : "=r"(a) : "l"(p));
    return a;
}
__device__ __forceinline__ void ldsm4(uint32_t* r, uint32_t a) {
    asm volatile("ldmatrix.sync.aligned.m8n8.x4.shared.b16 {%0,%1,%2,%3}, [%4];"
                 : "=r"(r[0]), "=r"(r[1]), "=r"(r[2]), "=r"(r[3]) : "r"(a));
}
__device__ __forceinline__ void ldsm2(uint32_t* r, uint32_t a) {
    asm volatile("ldmatrix.sync.aligned.m8n8.x2.shared.b16 {%0,%1}, [%2];"
                 : "=r"(r[0]), "=r"(r[1]) : "r"(a));
}
__device__ __forceinline__ void mma_tf32(float* c, const uint32_t* a,
                                         uint32_t b0, uint32_t b1) {
    asm volatile(
        "mma.sync.aligned.m16n8k8.row.col.f32.tf32.tf32.f32 "
        "{%0,%1,%2,%3}, {%4,%5,%6,%7}, {%8,%9}, {%0,%1,%2,%3};"
        : "+f"(c[0]), "+f"(c[1]), "+f"(c[2]), "+f"(c[3])
        : "r"(a[0]), "r"(a[1]), "r"(a[2]), "r"(a[3]), "r"(b0), "r"(b1));
}
__device__ __forceinline__ void cpasync16(uint32_t dst, const void* src) {
    asm volatile("cp.async.cg.shared.global [%0], [%1], 16;"
                 :: "r"(dst), "l"(src) : "memory");
}
// zero-fills when srcsz == 0
__device__ __forceinline__ void cpasync16z(uint32_t dst, const void* src,
                                           uint32_t srcsz) {
    asm volatile("cp.async.cg.shared.global [%0], [%1], 16, %2;"
                 :: "r"(dst), "l"(src), "r"(srcsz) : "memory");
}
__device__ __forceinline__ void cp_commit() {
    asm volatile("cp.async.commit_group;" ::: "memory");
}
__device__ __forceinline__ void cp_wait1() {
    asm volatile("cp.async.wait_group 1;" ::: "memory");
}
__device__ __forceinline__ void cp_wait0() {
    asm volatile("cp.async.wait_group 0;" ::: "memory");
}
__device__ __forceinline__ uint32_t tf32rn(float s) {
    uint32_t u;
    asm("cvt.rn.tf32.f32 %0, %1;" : "=r"(u) : "f"(s));
    return u;
}

// ---------------------------------------------------------------------------
// Prep (weight fuse): 48 blocks x 256 thr; block bd owns d in [16bd, 16bd+16).
//   Wc[c][d] = sum_h W2[c][h] * W1[h][d], tf32-rounded, SW128 swizzled tiles.
// ---------------------------------------------------------------------------
#define W2LD 102
#define PT 256

__global__ void __launch_bounds__(PT)
prep_kernel(const float* __restrict__ W1,
            const float* __restrict__ b1,
            const float* __restrict__ W2,
            const float* __restrict__ b2) {
    __shared__ float w1s[H_ * 16];      // [h][dd]
    __shared__ float w2s[NB * W2LD];    // [c][h] padded
    const int t = threadIdx.x;
    const int d0 = blockIdx.x * 16;

    for (int i = t; i < H_ * 16; i += PT)
        w1s[i] = W1[(i >> 4) * D_ + d0 + (i & 15)];
    for (int i = t; i < NB * H_; i += PT) {
        const int c = i / H_, h = i - c * H_;
        w2s[c * W2LD + h] = (c < C_) ? W2[i] : 0.0f;
    }
    __syncthreads();

    const int c3 = t >> 4;   // c group: 3*c3 .. 3*c3+2
    const int dd = t & 15;   // one d
    const int d  = d0 + dd;

    float acc[3] = {0.f, 0.f, 0.f};
#pragma unroll 4
    for (int h = 0; h < H_; h++) {
        const float w1v = w1s[h * 16 + dd];
#pragma unroll
        for (int ci = 0; ci < 3; ci++)
            acc[ci] = fmaf(w2s[(c3 * 3 + ci) * W2LD + h], w1v, acc[ci]);
    }

    const int ch = d >> 7;
    const int ka = (d >> 5) & 3;
    unsigned char* base = g_Wb + ch * BCH + ka * BSUB;
#pragma unroll
    for (int ci = 0; ci < 3; ci++) {
        const int c = c3 * 3 + ci;
        const uint32_t off = (uint32_t)c * 128 + (uint32_t)(d & 31) * 4;
        *(uint32_t*)(base + SW(off)) = tf32rn(acc[ci]);
    }

    if (blockIdx.x == 0 && t < NB) {
        float cv = 0.0f;
        if (t < C_) {
            for (int h = 0; h < H_; h++) cv += W2[t * H_ + h] * b1[h];
            cv += b2[t];
        }
        g_cvec[t] = cv;
    }
}

// ---------------------------------------------------------------------------
// GEMM via mma.sync tf32, 1024 threads, 4-way k-split across warp quarters.
// CTA = 64 rows x 48 cols, 32 warps. Quarter q consumes ka subtile q;
// partials reduced through stage-0/1 smem (free after last publish barrier).
// A: cp.async 3-stage pipeline (f32 bits = tf32). B: cp.async of pre-swizzled
// weights (ldsm2 from smem). One barrier per chunk.
// ---------------------------------------------------------------------------
extern "C" __global__ void __launch_bounds__(GT, 1)
gemm_kernel(const float* __restrict__ x,
            const int* __restrict__ valid_ids,
            float* __restrict__ out) {
    extern __shared__ unsigned char smem_raw[];
    __shared__ int s_wsum[17];
    const uint32_t sb_raw = smem_u32(smem_raw);
    const uint32_t pad = (1024u - (sb_raw & 1023u)) & 1023u;
    unsigned char* sm = smem_raw + pad;
    const uint32_t sb = sb_raw + pad;

    float* redS = (float*)sm;                // stage0/1 reuse: 3 x 3072 floats
    float* cS   = (float*)(sm + OFF_CVEC);
    int*   gS   = (int*)(sm + OFF_GS);

    const int tid  = threadIdx.x;
    const int lane = tid & 31, w = tid >> 5;     // w: 0..31
    const int row0 = blockIdx.x * BM;
    const int b    = row0 >> 9;          // batch
    const int seg  = row0 & (L_ - 1);    // segment start within batch

    // ---- Inline compaction: threads 0..511, 1 element each ----
    if (tid < L_) {
        const int v = (valid_ids[b * L_ + tid] == 1);
        const unsigned mask = __ballot_sync(0xffffffffu, v);
        const int wprefix = __popc(mask & ((1u << lane) - 1u));
        if (lane == 0) s_wsum[w] = __popc(mask);
        if (tid < BM) gS[tid] = -1;
        if (tid < NB) cS[tid] = g_cvec[tid];
        __syncthreads();
        if (tid == 0) {
            int run = 0;
#pragma unroll
            for (int i = 0; i < 16; i++) { int t2 = s_wsum[i]; s_wsum[i] = run; run += t2; }
            s_wsum[16] = run;
        }
        __syncthreads();
        const int pos = s_wsum[w] + wprefix;
        if (v && pos >= seg && pos < seg + BM) gS[pos - seg] = tid;
    } else {
        __syncthreads();
        __syncthreads();
    }
    const int total = s_wsum[16];
    __syncthreads();

    // Fully-constant block: output is cvec everywhere.
    if (total <= seg) {
        float* o = out + (size_t)row0 * C_;
        for (int i = tid; i < BM * C_; i += GT)
            o[i] = cS[i % C_];
        return;
    }

    // Producer mapping: thread -> A row r, slot sl, subtiles {kb, kb+2}
    const int r  = (tid >> 3) & 63;
    const int sl = tid & 7;
    const int kb = tid >> 9;             // 0 or 1
    const int src = gS[r];
    const uint32_t srcsz = (src >= 0) ? 16u : 0u;
    const float* xrow = x + ((size_t)b * L_ + (src >= 0 ? src : 0)) * D_;
    const uint32_t xs = (((uint32_t)r * 128) >> 3) & 0x70;
    const uint32_t adst = ((uint32_t)r * 128 + (uint32_t)sl * 16) ^ xs;

    // Consumer mapping: 32 warps; quarter = ka, (rw,cw) tile within quarter
    const int quarter = w >> 3;          // ka subtile 0..3
    const int wl = w & 7;
    const int rw = wl & 3;               // rows 16rw..16rw+15
    const int cw = wl >> 2;              // cols 24cw..24cw+23
    const uint32_t aoff = (uint32_t)(rw * 16 + (lane & 15)) * 128
                        + (uint32_t)((lane >> 4) << 4);
    const uint32_t xa   = (aoff >> 3) & 0x70;
    const int l16 = lane & 15;
    uint32_t boff[3], xb[3];
#pragma unroll
    for (int j = 0; j < 3; j++) {
        boff[j] = (uint32_t)(cw * 24 + j * 8 + (l16 & 7)) * 128
                + (uint32_t)((l16 >> 3) << 4);
        xb[j]   = (boff[j] >> 3) & 0x70;
    }

    // Group issue: B (pre-swizzled linear copy) + A (gathered, swizzled dst)
    auto issue_group = [&](int g) {
        const uint32_t bufs = sb + (g % NSTG) * BUFSZ;
        const unsigned char* bs = g_Wb + g * BCH;
        const uint32_t bd = bufs + ATOT;
        cpasync16(bd + tid * 16, bs + tid * 16);
        if (tid < 512)
            cpasync16(bd + (1024 + tid) * 16, bs + (1024 + tid) * 16);
        const float* xc = xrow + g * 128;
        cpasync16z(bufs + kb * ASUB + adst,       xc + kb * 32 + sl * 4,       srcsz);
        cpasync16z(bufs + (kb + 2) * ASUB + adst, xc + (kb + 2) * 32 + sl * 4, srcsz);
        cp_commit();
    };

    // Prologue: stages 0,1 in flight
    issue_group(0);
    issue_group(1);

    float acc[3][4];
#pragma unroll
    for (int j = 0; j < 3; j++)
#pragma unroll
        for (int k = 0; k < 4; k++) acc[j][k] = 0.f;

    for (int ch = 0; ch < NCHUNK; ch++) {
        if (ch < NCHUNK - 1) cp_wait1(); else cp_wait0();
        __syncthreads();
        if (ch + 2 < NCHUNK) issue_group(ch + 2);

        const uint32_t bufs = sb + (ch % NSTG) * BUFSZ;
        const uint32_t aA = bufs + quarter * ASUB;
        const uint32_t bK = bufs + ATOT + quarter * BSUB;

        // This quarter consumes its ka subtile: 4 k8-steps x 3 n-tiles
#pragma unroll
        for (int s = 0; s < 4; s++) {
            uint32_t ah[4];
            ldsm4(ah, aA + ((aoff + 32u * s) ^ xa));
#pragma unroll
            for (int j = 0; j < 3; j++) {
                uint32_t bv[2];
                ldsm2(bv, bK + ((boff[j] + 32u * s) ^ xb[j]));
                mma_tf32(acc[j], ah, bv[0], bv[1]);
            }
        }
    }

    // ---- Reduce the four k-quarters through smem (stages 0/1 now free) ----
    const int rrow = rw * 16 + (lane >> 2);
    if (quarter != 0) {
        float* rq = redS + (quarter - 1) * 3072;
#pragma unroll
        for (int j = 0; j < 3; j++) {
            const int cb = cw * 24 + j * 8 + (lane & 3) * 2;
#pragma unroll
            for (int h = 0; h < 2; h++)
                *(float2*)(rq + (rrow + 8 * h) * NB + cb)
                    = make_float2(acc[j][2 * h], acc[j][2 * h + 1]);
        }
    }
    __syncthreads();

    if (quarter == 0) {
        const int rbase = row0 + rrow;
#pragma unroll
        for (int j = 0; j < 3; j++) {
            const int cb = cw * 24 + j * 8 + (lane & 3) * 2;
            const float c0 = cS[cb], c1 = cS[cb + 1];
#pragma unroll
            for (int h = 0; h < 2; h++) {
                const int ro = (rrow + 8 * h) * NB + cb;
                const float2 p1 = *(const float2*)(redS + ro);
                const float2 p2 = *(const float2*)(redS + 3072 + ro);
                const float2 p3 = *(const float2*)(redS + 6144 + ro);
                float* o = out + (size_t)(rbase + 8 * h) * C_;
                if (cb < C_)
                    o[cb] = acc[j][2 * h] + p1.x + p2.x + p3.x + c0;
                if (cb + 1 < C_)
                    o[cb + 1] = acc[j][2 * h + 1] + p1.y + p2.y + p3.y + c1;
            }
        }
    }
}

// ---------------------------------------------------------------------------
extern "C" void kernel_launch(void* const* d_in, const int* in_sizes, int n_in,
                              void* d_out, int out_size) {
    const float* x   = (const float*)d_in[0];   // (32,512,768) f32
    const int*   vid = (const int*)  d_in[1];   // (32,512) i32
    const float* W1  = (const float*)d_in[2];   // (100,768)
    const float* b1  = (const float*)d_in[3];   // (100,)
    const float* W2  = (const float*)d_in[4];   // (45,100)
    const float* b2  = (const float*)d_in[5];   // (45,)
    float* out = (float*)d_out;                 // (16384,45)

    static bool attr_set = false;
    if (!attr_set) {
        cudaFuncSetAttribute(gemm_kernel,
                             cudaFuncAttributeMaxDynamicSharedMemorySize,
                             SMEM_BYTES);
        attr_set = true;
    }

    prep_kernel<<<48, PT>>>(W1, b1, W2, b2);
    gemm_kernel<<<M_ / BM, GT, SMEM_BYTES>>>(x, vid, out);
}

// round 14
// speedup vs baseline: 1.0816x; 1.0816x over previous
#include <cuda_runtime.h>
#include <cstdint>

// Problem shape (fixed)
#define B_  32
#define L_  512
#define D_  768
#define H_  100
#define C_  45
#define M_  (B_ * L_)           // 16384 rows
#define NB  48                  // padded N
#define BM  64                  // rows per CTA -> 256 CTAs
#define NCHUNK 6                // 6 chunks of 128 f32 k
#define GT  512
#define NSTG 4                  // cp.async pipeline stages (deepened 3->4)

#define ASUB 8192               // A subtile (64 rows * 128B = 32 f32 k)
#define ATOT 32768              // A per stage (4 subtiles, k=128)
#define BSUB 6144               // B subtile (48 rows * 128B)
#define BTOT 24576              // B per stage (4 subtiles)
#define BCH  BTOT               // B bytes per chunk in global
#define BUFSZ (ATOT + BTOT)     // 57344 per stage
// Reduction buffer reuses stage 0 (chunk 4's stage; consumed before reduce).
#define OFF_CVEC (NSTG*BUFSZ)   // 229376
#define OFF_GS   (OFF_CVEC + 192)
#define SMEM_USE (OFF_GS + 256)
#define SMEM_BYTES (SMEM_USE + 1024)   // 230848 <= 232448 cap

#define SW(o) ((o) ^ (((o) >> 3) & 0x70))

// Device scratch. g_Wb: fused weight, tf32(f32) SW128 pre-swizzled.
// Layout: [chunk 0..5][ka 0..3][48 rows x 128B].
__device__ unsigned char g_Wb[NCHUNK * BCH];
__device__ float g_cvec[NB];

// ---------------------------------------------------------------------------
// PTX helpers (arch-portable: ldmatrix sm_75+, mma.tf32 sm_80+, cp.async sm_80+)
// ---------------------------------------------------------------------------
__device__ __forceinline__ uint32_t smem_u32(const void* p) {
    uint32_t a;
    asm("{ .reg .u64 t; cvta.to.shared.u64 t, %1; cvt.u32.u64 %0, t; }"
        : "=r"(a) : "l"(p));
    return a;
}
__device__ __forceinline__ void ldsm4(uint32_t* r, uint32_t a) {
    asm volatile("ldmatrix.sync.aligned.m8n8.x4.shared.b16 {%0,%1,%2,%3}, [%4];"
                 : "=r"(r[0]), "=r"(r[1]), "=r"(r[2]), "=r"(r[3]) : "r"(a));
}
__device__ __forceinline__ void ldsm2(uint32_t* r, uint32_t a) {
    asm volatile("ldmatrix.sync.aligned.m8n8.x2.shared.b16 {%0,%1}, [%2];"
                 : "=r"(r[0]), "=r"(r[1]) : "r"(a));
}
__device__ __forceinline__ void mma_tf32(float* c, const uint32_t* a,
                                         uint32_t b0, uint32_t b1) {
    asm volatile(
        "mma.sync.aligned.m16n8k8.row.col.f32.tf32.tf32.f32 "
        "{%0,%1,%2,%3}, {%4,%5,%6,%7}, {%8,%9}, {%0,%1,%2,%3};"
        : "+f"(c[0]), "+f"(c[1]), "+f"(c[2]), "+f"(c[3])
        : "r"(a[0]), "r"(a[1]), "r"(a[2]), "r"(a[3]), "r"(b0), "r"(b1));
}
__device__ __forceinline__ void cpasync16(uint32_t dst, const void* src) {
    asm volatile("cp.async.cg.shared.global [%0], [%1], 16;"
                 :: "r"(dst), "l"(src) : "memory");
}
// zero-fills when srcsz == 0
__device__ __forceinline__ void cpasync16z(uint32_t dst, const void* src,
                                           uint32_t srcsz) {
    asm volatile("cp.async.cg.shared.global [%0], [%1], 16, %2;"
                 :: "r"(dst), "l"(src), "r"(srcsz) : "memory");
}
__device__ __forceinline__ void cp_commit() {
    asm volatile("cp.async.commit_group;" ::: "memory");
}
__device__ __forceinline__ void cp_wait2() {
    asm volatile("cp.async.wait_group 2;" ::: "memory");
}
__device__ __forceinline__ void cp_wait1() {
    asm volatile("cp.async.wait_group 1;" ::: "memory");
}
__device__ __forceinline__ void cp_wait0() {
    asm volatile("cp.async.wait_group 0;" ::: "memory");
}
__device__ __forceinline__ uint32_t tf32rn(float s) {
    uint32_t u;
    asm("cvt.rn.tf32.f32 %0, %1;" : "=r"(u) : "f"(s));
    return u;
}

// ---------------------------------------------------------------------------
// Prep (weight fuse): 48 blocks x 256 thr; block bd owns d in [16bd, 16bd+16).
//   Wc[c][d] = sum_h W2[c][h] * W1[h][d], tf32-rounded, SW128 swizzled tiles.
// ---------------------------------------------------------------------------
#define W2LD 102
#define PT 256

__global__ void __launch_bounds__(PT)
prep_kernel(const float* __restrict__ W1,
            const float* __restrict__ b1,
            const float* __restrict__ W2,
            const float* __restrict__ b2) {
    __shared__ float w1s[H_ * 16];      // [h][dd]
    __shared__ float w2s[NB * W2LD];    // [c][h] padded
    const int t = threadIdx.x;
    const int d0 = blockIdx.x * 16;

    for (int i = t; i < H_ * 16; i += PT)
        w1s[i] = W1[(i >> 4) * D_ + d0 + (i & 15)];
    for (int i = t; i < NB * H_; i += PT) {
        const int c = i / H_, h = i - c * H_;
        w2s[c * W2LD + h] = (c < C_) ? W2[i] : 0.0f;
    }
    __syncthreads();

    const int c3 = t >> 4;   // c group: 3*c3 .. 3*c3+2
    const int dd = t & 15;   // one d
    const int d  = d0 + dd;

    float acc[3] = {0.f, 0.f, 0.f};
#pragma unroll 4
    for (int h = 0; h < H_; h++) {
        const float w1v = w1s[h * 16 + dd];
#pragma unroll
        for (int ci = 0; ci < 3; ci++)
            acc[ci] = fmaf(w2s[(c3 * 3 + ci) * W2LD + h], w1v, acc[ci]);
    }

    const int ch = d >> 7;
    const int ka = (d >> 5) & 3;
    unsigned char* base = g_Wb + ch * BCH + ka * BSUB;
#pragma unroll
    for (int ci = 0; ci < 3; ci++) {
        const int c = c3 * 3 + ci;
        const uint32_t off = (uint32_t)c * 128 + (uint32_t)(d & 31) * 4;
        *(uint32_t*)(base + SW(off)) = tf32rn(acc[ci]);
    }

    if (blockIdx.x == 0 && t < NB) {
        float cv = 0.0f;
        if (t < C_) {
            for (int h = 0; h < H_; h++) cv += W2[t * H_ + h] * b1[h];
            cv += b2[t];
        }
        g_cvec[t] = cv;
    }
}

// ---------------------------------------------------------------------------
// GEMM via mma.sync tf32, 512 threads, k-split across warp halves.
// CTA = 64 rows x 48 cols. Warps 0-7 consume ka{0,1}, warps 8-15 ka{2,3};
// partials reduced through stage-0 smem (free after the last barrier).
// A+B: cp.async 4-stage pipeline, lookahead 3 chunks (covers DRAM latency).
// One barrier per chunk.
// ---------------------------------------------------------------------------
extern "C" __global__ void __launch_bounds__(GT, 1)
gemm_kernel(const float* __restrict__ x,
            const int* __restrict__ valid_ids,
            float* __restrict__ out) {
    extern __shared__ unsigned char smem_raw[];
    __shared__ int s_wsum[17];
    const uint32_t sb_raw = smem_u32(smem_raw);
    const uint32_t pad = (1024u - (sb_raw & 1023u)) & 1023u;
    unsigned char* sm = smem_raw + pad;
    const uint32_t sb = sb_raw + pad;

    float* redS = (float*)sm;                // stage-0 reuse: 64x48 f32
    float* cS   = (float*)(sm + OFF_CVEC);
    int*   gS   = (int*)(sm + OFF_GS);

    const int tid  = threadIdx.x;
    const int row0 = blockIdx.x * BM;
    const int b    = row0 >> 9;          // batch
    const int seg  = row0 & (L_ - 1);    // segment start within batch

    // ---- Inline compaction: 1 element/thread ballot scan ----
    const int lane = tid & 31, w = tid >> 5;     // w: 0..15
    const int v = (valid_ids[b * L_ + tid] == 1);
    const unsigned mask = __ballot_sync(0xffffffffu, v);
    const int wprefix = __popc(mask & ((1u << lane) - 1u));
    if (lane == 0) s_wsum[w] = __popc(mask);
    if (tid < BM) gS[tid] = -1;
    if (tid < NB) cS[tid] = g_cvec[tid];
    __syncthreads();
    if (tid == 0) {
        int run = 0;
#pragma unroll
        for (int i = 0; i < 16; i++) { int t = s_wsum[i]; s_wsum[i] = run; run += t; }
        s_wsum[16] = run;
    }
    __syncthreads();
    {
        const int pos = s_wsum[w] + wprefix;
        if (v && pos >= seg && pos < seg + BM) gS[pos - seg] = tid;
    }
    const int total = s_wsum[16];
    __syncthreads();

    // Fully-constant block: output is cvec everywhere.
    if (total <= seg) {
        float* o = out + (size_t)row0 * C_;
        for (int i = tid; i < BM * C_; i += GT)
            o[i] = cS[i % C_];
        return;
    }

    // Producer mapping: thread -> A row r = tid>>3, 16B slot s = tid&7
    const int r = tid >> 3;
    const int sl = tid & 7;
    const int src = gS[r];
    const uint32_t srcsz = (src >= 0) ? 16u : 0u;
    const float* xrow = x + ((size_t)b * L_ + (src >= 0 ? src : 0)) * D_;
    const uint32_t xs = (((uint32_t)r * 128) >> 3) & 0x70;  // row swizzle bits
    const uint32_t adst = ((uint32_t)r * 128 + (uint32_t)sl * 16) ^ xs;

    // Consumer mapping: 16 warps; half = k-split, (rw,cw) tile within half
    const int half = w >> 3;             // 0: ka{0,1}, 1: ka{2,3}
    const int wl   = w & 7;
    const int rw   = wl & 3;             // rows 16rw..16rw+15
    const int cw   = wl >> 2;            // cols 24cw..24cw+23
    const uint32_t aoff = (uint32_t)(rw * 16 + (lane & 15)) * 128
                        + (uint32_t)((lane >> 4) << 4);
    const uint32_t xa   = (aoff >> 3) & 0x70;
    const int l16 = lane & 15;
    uint32_t boff[3], xb[3];
#pragma unroll
    for (int j = 0; j < 3; j++) {
        boff[j] = (uint32_t)(cw * 24 + j * 8 + (l16 & 7)) * 128
                + (uint32_t)((l16 >> 3) << 4);
        xb[j]   = (boff[j] >> 3) & 0x70;
    }

    // Group issue: B (pre-swizzled linear copy) + A (gathered, swizzled dst)
    auto issue_group = [&](int g) {
        const uint32_t bufs = sb + (g % NSTG) * BUFSZ;
        const unsigned char* bs = g_Wb + g * BCH;
        const uint32_t bd = bufs + ATOT;
#pragma unroll
        for (int idx = 0; idx < 3; idx++)
            cpasync16(bd + (tid + idx * GT) * 16, bs + (tid + idx * GT) * 16);
        const float* xc = xrow + g * 128;
#pragma unroll
        for (int ka = 0; ka < 4; ka++)
            cpasync16z(bufs + ka * ASUB + adst, xc + ka * 32 + sl * 4, srcsz);
        cp_commit();
    };

    // Prologue: stages 0,1,2 in flight
    issue_group(0);
    issue_group(1);
    issue_group(2);

    float acc[3][4];
#pragma unroll
    for (int j = 0; j < 3; j++)
#pragma unroll
        for (int k = 0; k < 4; k++) acc[j][k] = 0.f;

    for (int ch = 0; ch < NCHUNK; ch++) {
        // Wait for group ch: outstanding after = {ch+1 .. min(ch+2, 5)}
        if (ch <= 3)      cp_wait2();
        else if (ch == 4) cp_wait1();
        else              cp_wait0();
        __syncthreads();
        // Stage (ch+3)%NSTG == (ch-1)%NSTG, freed by the barrier above.
        if (ch + 3 < NCHUNK) issue_group(ch + 3);

        const uint32_t bufs = sb + (ch % NSTG) * BUFSZ;
        const uint32_t bB = bufs + ATOT;

        // This half consumes its 2 ka subtiles: 8 k8-steps x 3 n-tiles
#pragma unroll
        for (int s8 = 0; s8 < 8; s8++) {
            const int ka = half * 2 + (s8 >> 2), s = s8 & 3;
            const uint32_t aA = bufs + ka * ASUB;
            const uint32_t bK = bB + ka * BSUB;
            uint32_t ah[4];
            ldsm4(ah, aA + ((aoff + 32u * s) ^ xa));
#pragma unroll
            for (int j = 0; j < 3; j++) {
                uint32_t bv[2];
                ldsm2(bv, bK + ((boff[j] + 32u * s) ^ xb[j]));
                mma_tf32(acc[j], ah, bv[0], bv[1]);
            }
        }
    }

    // ---- Reduce the two k-halves through stage-0 smem ----
    // Stage 0 held chunk 4, consumed before the ch=5 barrier; chunk 5 lives
    // in stage 1, so these writes race with nothing.
    const int rrow = rw * 16 + (lane >> 2);
    if (half == 1) {
#pragma unroll
        for (int j = 0; j < 3; j++) {
            const int cb = cw * 24 + j * 8 + (lane & 3) * 2;
#pragma unroll
            for (int h = 0; h < 2; h++)
                *(float2*)(redS + (rrow + 8 * h) * NB + cb)
                    = make_float2(acc[j][2 * h], acc[j][2 * h + 1]);
        }
    }
    __syncthreads();

    if (half == 0) {
        const int rbase = row0 + rrow;
#pragma unroll
        for (int j = 0; j < 3; j++) {
            const int cb = cw * 24 + j * 8 + (lane & 3) * 2;
            const float c0 = cS[cb], c1 = cS[cb + 1];
#pragma unroll
            for (int h = 0; h < 2; h++) {
                const float2 p = *(const float2*)(redS + (rrow + 8 * h) * NB + cb);
                float* o = out + (size_t)(rbase + 8 * h) * C_;
                if (cb < C_)     o[cb]     = acc[j][2 * h]     + p.x + c0;
                if (cb + 1 < C_) o[cb + 1] = acc[j][2 * h + 1] + p.y + c1;
            }
        }
    }
}

// ---------------------------------------------------------------------------
extern "C" void kernel_launch(void* const* d_in, const int* in_sizes, int n_in,
                              void* d_out, int out_size) {
    const float* x   = (const float*)d_in[0];   // (32,512,768) f32
    const int*   vid = (const int*)  d_in[1];   // (32,512) i32
    const float* W1  = (const float*)d_in[2];   // (100,768)
    const float* b1  = (const float*)d_in[3];   // (100,)
    const float* W2  = (const float*)d_in[4];   // (45,100)
    const float* b2  = (const float*)d_in[5];   // (45,)
    float* out = (float*)d_out;                 // (16384,45)

    static bool attr_set = false;
    if (!attr_set) {
        cudaFuncSetAttribute(gemm_kernel,
                             cudaFuncAttributeMaxDynamicSharedMemorySize,
                             SMEM_BYTES);
        attr_set = true;
    }

    prep_kernel<<<48, PT>>>(W1, b1, W2, b2);
    gemm_kernel<<<M_ / BM, GT, SMEM_BYTES>>>(x, vid, out);
}